// round 2
// baseline (speedup 1.0000x reference)
#include <cuda_runtime.h>
#include <math.h>

// Problem constants (fixed shapes per metadata)
//   x: [B=2, C=64, L=8, H=128, W=128] fp32
//   patches P=8 -> nH=nW=16, N = B*256 patches, 8 L-slices each
#define NUM_C 64
#define NUM_E 8

typedef unsigned long long u64;

__device__ int   g_topi[2048];
__device__ float g_topw[2048];

__device__ __forceinline__ u64 pack2(float a, float b) {
    u64 r; asm("mov.b64 %0, {%1, %2};" : "=l"(r) : "f"(a), "f"(b)); return r;
}
__device__ __forceinline__ float2 unpack2(u64 v) {
    float2 r; asm("mov.b64 {%0, %1}, %2;" : "=f"(r.x), "=f"(r.y) : "l"(v)); return r;
}
__device__ __forceinline__ void fma2(u64 &d, u64 a, u64 b) {
    asm("fma.rn.f32x2 %0, %1, %2, %0;" : "+l"(d) : "l"(a), "l"(b));
}

// Shared memory layout for main kernel.
// Activation arrays padded to stride 68 (68 % 32 == 4) to break channel-stride
// bank conflicts while keeping 16B alignment for float4 access at p0 multiples of 4.
// Weight arrays padded to stride 65 (65 % 32 == 1) so GEMM reads
// w[(lane+32m)*65 + c] hit 32 distinct banks.
struct SmemLayout {
    float xs  [64 * 68];   // input slice  [c][p]
    float h   [64 * 68];   // LN output, later gated activations [c][p]
    float h2  [128 * 68];  // pw_in output [o][p]
    float win [128 * 65];  // pw_in weights [o][c]
    float wout[64 * 65];   // pw_out weights [o][c]
    float dw  [64 * 49];   // depthwise weights [c][7*7]
    float lnw [64];
    float lnb [64];
    float bin [128];
    float bout[64];
};

// ---------------------------------------------------------------------------
// Kernel 1: router. One block per patch. 256 threads: 4 threads per channel.
// ---------------------------------------------------------------------------
__global__ __launch_bounds__(256) void router_kernel(
    const float* __restrict__ x,
    const float* __restrict__ rw,
    const float* __restrict__ rb)
{
    __shared__ float rmean[64];
    __shared__ float lg[8];
    const int n  = blockIdx.x;
    const int b  = n >> 8;
    const int ph = (n >> 4) & 15;
    const int pw = n & 15;
    const int t  = threadIdx.x;
    const int c  = t >> 2;
    const int part = t & 3;

    const float* xb = x + ((size_t)(b * 64 + c) * 8) * 16384 + (ph * 8) * 128 + pw * 8;
    float s = 0.f;
    #pragma unroll 4
    for (int k = 0; k < 16; ++k) {
        int rowid = part * 16 + k;          // 0..63 over (l, r)
        int l = rowid >> 3, r = rowid & 7;
        const float* p = xb + (size_t)l * 16384 + r * 128;
        float4 v0 = *reinterpret_cast<const float4*>(p);
        float4 v1 = *reinterpret_cast<const float4*>(p + 4);
        s += v0.x + v0.y + v0.z + v0.w + v1.x + v1.y + v1.z + v1.w;
    }
    s += __shfl_xor_sync(0xffffffffu, s, 1);
    s += __shfl_xor_sync(0xffffffffu, s, 2);
    if (part == 0) rmean[c] = s * (1.0f / 512.0f);
    __syncthreads();

    if (t < 8) {
        float acc = rb[t];
        #pragma unroll 8
        for (int cc = 0; cc < 64; ++cc) acc += rw[t * 64 + cc] * rmean[cc];
        lg[t] = acc;
    }
    __syncthreads();

    if (t == 0) {
        // top-2 with first-index tie-breaking (matches lax.top_k stability)
        int i0 = 0; float v0 = lg[0];
        #pragma unroll
        for (int e = 1; e < 8; ++e) if (lg[e] > v0) { v0 = lg[e]; i0 = e; }
        int i1 = -1; float v1 = -1e30f;
        #pragma unroll
        for (int e = 0; e < 8; ++e) if (e != i0 && lg[e] > v1) { v1 = lg[e]; i1 = e; }
        float w0 = 1.0f / (1.0f + expf(v1 - v0));
        g_topi[n * 2]     = i0;
        g_topi[n * 2 + 1] = i1;
        g_topw[n * 2]     = w0;
        g_topw[n * 2 + 1] = 1.0f - w0;
    }
}

// ---------------------------------------------------------------------------
// Kernel 2: main MoE compute. One CTA per (patch, l) slice. 256 threads.
// out = x + sum_{top2} w_e * f_e(x_slice)
// ---------------------------------------------------------------------------
__global__ __launch_bounds__(256, 1) void moe_main_kernel(
    const float* __restrict__ x,
    const float* __restrict__ dw_w,
    const float* __restrict__ ln_w,
    const float* __restrict__ ln_b,
    const float* __restrict__ pw_in_w,
    const float* __restrict__ pw_in_b,
    const float* __restrict__ pw_out_w,
    const float* __restrict__ pw_out_b,
    float* __restrict__ out)
{
    extern __shared__ char smem_raw[];
    SmemLayout& S = *reinterpret_cast<SmemLayout*>(smem_raw);

    const int t = threadIdx.x;
    const int slice = blockIdx.x;
    const int n  = slice >> 3;
    const int l  = slice & 7;
    const int b  = n >> 8;
    const int ph = (n >> 4) & 15;
    const int pw = n & 15;
    // global base for this (b, l, patch) at channel 0
    const size_t gslice = (size_t)(b * 64) * 8 * 16384 + (size_t)l * 16384
                        + (ph * 8) * 128 + pw * 8;

    // ---- load x slice into smem (padded stride 68) ----
    #pragma unroll
    for (int k = 0; k < 4; ++k) {
        int id = t + k * 256;           // 1024 float4s total
        int c = id >> 4;
        int r = (id >> 1) & 7;
        int half = id & 1;
        const float* src = x + gslice + (size_t)c * (8 * 16384) + r * 128 + half * 4;
        *reinterpret_cast<float4*>(S.xs + c * 68 + r * 8 + half * 4) =
            *reinterpret_cast<const float4*>(src);
    }

    const int   e0i = g_topi[n * 2];
    const int   e1i = g_topi[n * 2 + 1];
    const float w0v = g_topw[n * 2];
    const float w1v = g_topw[n * 2 + 1];

    float outacc[2][8];
    #pragma unroll
    for (int m = 0; m < 2; ++m)
        #pragma unroll
        for (int j = 0; j < 8; ++j) outacc[m][j] = 0.f;

    for (int ei = 0; ei < 2; ++ei) {
        const int   e  = (ei == 0) ? e0i : e1i;
        const float we = (ei == 0) ? w0v : w1v;

        __syncthreads();  // xs ready (iter 0) / prior expert's smem reads done (iter 1)

        // ---- stage expert weights ----
        {
            const float* wsrc = pw_in_w + e * 8192;
            #pragma unroll
            for (int k = 0; k < 8; ++k) {
                int i4 = t + k * 256;     // 2048 float4s
                float4 v = *reinterpret_cast<const float4*>(wsrc + i4 * 4);
                int o = (i4 * 4) >> 6, c = (i4 * 4) & 63;
                float* d = S.win + o * 65 + c;
                d[0] = v.x; d[1] = v.y; d[2] = v.z; d[3] = v.w;
            }
            const float* wsrc2 = pw_out_w + e * 4096;
            #pragma unroll
            for (int k = 0; k < 4; ++k) {
                int i4 = t + k * 256;     // 1024 float4s
                float4 v = *reinterpret_cast<const float4*>(wsrc2 + i4 * 4);
                int o = (i4 * 4) >> 6, c = (i4 * 4) & 63;
                float* d = S.wout + o * 65 + c;
                d[0] = v.x; d[1] = v.y; d[2] = v.z; d[3] = v.w;
            }
            const float* dsrc = dw_w + e * 3136;
            #pragma unroll
            for (int k = 0; k < 4; ++k) {
                int i4 = t + k * 256;
                if (i4 < 784)
                    *reinterpret_cast<float4*>(S.dw + i4 * 4) =
                        *reinterpret_cast<const float4*>(dsrc + i4 * 4);
            }
            if (t < 64) {
                S.lnw[t]  = ln_w[e * 64 + t];
                S.lnb[t]  = ln_b[e * 64 + t];
                S.bout[t] = pw_out_b[e * 64 + t];
            }
            if (t < 128) S.bin[t] = pw_in_b[e * 128 + t];
        }
        __syncthreads();

        // ---- depthwise 7x7 (SAME on 8x8) + LayerNorm -> S.h ----
        // thread: c = t/4, rows y0 = 2*(t%4), y0+1
        {
            const int c = t >> 2, q = t & 3, y0 = q << 1;
            float a0[8], a1[8];
            #pragma unroll
            for (int i = 0; i < 8; ++i) { a0[i] = 0.f; a1[i] = 0.f; }
            const float* xc = S.xs + c * 68;
            const float* wc = S.dw + c * 49;
            #pragma unroll
            for (int yy = 0; yy < 8; ++yy) {
                int d0 = yy - y0;            // dy for row y0; row y0+1 has dy = d0-1
                if (d0 < -3 || d0 > 4) continue;
                float inp[14];
                #pragma unroll
                for (int i = 0; i < 3; ++i) { inp[i] = 0.f; inp[11 + i] = 0.f; }
                float4 va = *reinterpret_cast<const float4*>(xc + yy * 8);
                float4 vb = *reinterpret_cast<const float4*>(xc + yy * 8 + 4);
                inp[3] = va.x; inp[4] = va.y; inp[5]  = va.z; inp[6]  = va.w;
                inp[7] = vb.x; inp[8] = vb.y; inp[9]  = vb.z; inp[10] = vb.w;
                if (d0 >= -3 && d0 <= 3) {
                    const float* wr = wc + (d0 + 3) * 7;
                    float wv[7];
                    #pragma unroll
                    for (int j = 0; j < 7; ++j) wv[j] = wr[j];
                    #pragma unroll
                    for (int xx = 0; xx < 8; ++xx)
                        #pragma unroll
                        for (int j = 0; j < 7; ++j)
                            a0[xx] += wv[j] * inp[xx + j];
                }
                int d1 = d0 - 1;
                if (d1 >= -3 && d1 <= 3) {
                    const float* wr = wc + (d1 + 3) * 7;
                    float wv[7];
                    #pragma unroll
                    for (int j = 0; j < 7; ++j) wv[j] = wr[j];
                    #pragma unroll
                    for (int xx = 0; xx < 8; ++xx)
                        #pragma unroll
                        for (int j = 0; j < 7; ++j)
                            a1[xx] += wv[j] * inp[xx + j];
                }
            }
            // LayerNorm over 64 spatial values per channel (4 lanes per channel)
            float s = 0.f, s2 = 0.f;
            #pragma unroll
            for (int i = 0; i < 8; ++i) {
                s  += a0[i] + a1[i];
                s2 += a0[i] * a0[i] + a1[i] * a1[i];
            }
            s  += __shfl_xor_sync(0xffffffffu, s, 1);
            s  += __shfl_xor_sync(0xffffffffu, s, 2);
            s2 += __shfl_xor_sync(0xffffffffu, s2, 1);
            s2 += __shfl_xor_sync(0xffffffffu, s2, 2);
            const float mean = s * 0.015625f;
            const float var  = fmaxf(s2 * 0.015625f - mean * mean, 0.f);
            const float rstd = rsqrtf(var + 1e-5f);
            float* hc = S.h + c * 68;
            #pragma unroll
            for (int xx = 0; xx < 8; ++xx) {
                int p = y0 * 8 + xx;
                hc[p]     = (a0[xx] - mean) * rstd * S.lnw[p]     + S.lnb[p];
                hc[p + 8] = (a1[xx] - mean) * rstd * S.lnw[p + 8] + S.lnb[p + 8];
            }
        }
        __syncthreads();

        // ---- pw_in GEMM: h2[o][p] = sum_c win[o][c]*h[c][p] + bin[o] ----
        // thread tile: o in {og, og+32, og+64, og+96}, p in [p0, p0+8)
        {
            const int og = t & 31;
            const int p0 = (t >> 5) << 3;
            u64 acc[4][4];
            #pragma unroll
            for (int m = 0; m < 4; ++m)
                #pragma unroll
                for (int j = 0; j < 4; ++j) acc[m][j] = 0ull;
            #pragma unroll 4
            for (int c = 0; c < 64; ++c) {
                const float* hc = S.h + c * 68 + p0;
                ulonglong2 hA = *reinterpret_cast<const ulonglong2*>(hc);
                ulonglong2 hB = *reinterpret_cast<const ulonglong2*>(hc + 4);
                #pragma unroll
                for (int m = 0; m < 4; ++m) {
                    float w = S.win[(og + 32 * m) * 65 + c];
                    u64 wp = pack2(w, w);
                    fma2(acc[m][0], wp, hA.x);
                    fma2(acc[m][1], wp, hA.y);
                    fma2(acc[m][2], wp, hB.x);
                    fma2(acc[m][3], wp, hB.y);
                }
            }
            #pragma unroll
            for (int m = 0; m < 4; ++m) {
                int o = og + 32 * m;
                float bi = S.bin[o];
                float2 u0 = unpack2(acc[m][0]);
                float2 u1 = unpack2(acc[m][1]);
                float2 u2 = unpack2(acc[m][2]);
                float2 u3 = unpack2(acc[m][3]);
                float4 r0 = make_float4(u0.x + bi, u0.y + bi, u1.x + bi, u1.y + bi);
                float4 r1 = make_float4(u2.x + bi, u2.y + bi, u3.x + bi, u3.y + bi);
                float* d = S.h2 + o * 68 + p0;
                *reinterpret_cast<float4*>(d)     = r0;
                *reinterpret_cast<float4*>(d + 4) = r1;
            }
        }
        __syncthreads();

        // ---- gating: act[c][p] = silu(h2[c][p]) * h2[c+64][p] -> S.h ----
        {
            const int c  = t >> 2;
            const int cb = (t & 3) * 16;
            float* hc = S.h + c * 68;
            const float* aA = S.h2 + c * 68;
            const float* gG = S.h2 + (c + 64) * 68;
            #pragma unroll
            for (int k = 0; k < 4; ++k) {
                int col = cb + k * 4;
                float4 a = *reinterpret_cast<const float4*>(aA + col);
                float4 g = *reinterpret_cast<const float4*>(gG + col);
                float4 r;
                r.x = a.x / (1.f + __expf(-a.x)) * g.x;
                r.y = a.y / (1.f + __expf(-a.y)) * g.y;
                r.z = a.z / (1.f + __expf(-a.z)) * g.z;
                r.w = a.w / (1.f + __expf(-a.w)) * g.w;
                *reinterpret_cast<float4*>(hc + col) = r;
            }
        }
        __syncthreads();

        // ---- pw_out GEMM + weighted accumulate into registers ----
        // thread tile: o in {og, og+32}, p in [p0, p0+8)
        {
            const int og = t & 31;
            const int p0 = (t >> 5) << 3;
            u64 acc[2][4];
            #pragma unroll
            for (int m = 0; m < 2; ++m)
                #pragma unroll
                for (int j = 0; j < 4; ++j) acc[m][j] = 0ull;
            #pragma unroll 4
            for (int c = 0; c < 64; ++c) {
                const float* ac = S.h + c * 68 + p0;
                ulonglong2 hA = *reinterpret_cast<const ulonglong2*>(ac);
                ulonglong2 hB = *reinterpret_cast<const ulonglong2*>(ac + 4);
                float wa = S.wout[og * 65 + c];
                float wb = S.wout[(og + 32) * 65 + c];
                u64 wpa = pack2(wa, wa);
                u64 wpb = pack2(wb, wb);
                fma2(acc[0][0], wpa, hA.x);
                fma2(acc[0][1], wpa, hA.y);
                fma2(acc[0][2], wpa, hB.x);
                fma2(acc[0][3], wpa, hB.y);
                fma2(acc[1][0], wpb, hA.x);
                fma2(acc[1][1], wpb, hA.y);
                fma2(acc[1][2], wpb, hB.x);
                fma2(acc[1][3], wpb, hB.y);
            }
            #pragma unroll
            for (int m = 0; m < 2; ++m) {
                int o = og + 32 * m;
                float bo = S.bout[o];
                #pragma unroll
                for (int k = 0; k < 4; ++k) {
                    float2 u = unpack2(acc[m][k]);
                    outacc[m][2 * k]     += we * (u.x + bo);
                    outacc[m][2 * k + 1] += we * (u.y + bo);
                }
            }
        }
    }

    // ---- final write: out = x + accumulated expert residuals ----
    {
        const int r  = t >> 5;
        const int og = t & 31;
        #pragma unroll
        for (int m = 0; m < 2; ++m) {
            int c = og + 32 * m;
            const float* xp = S.xs + c * 68 + r * 8;
            float* dst = out + gslice + (size_t)c * (8 * 16384) + r * 128;
            float4 v0 = *reinterpret_cast<const float4*>(xp);
            float4 v1 = *reinterpret_cast<const float4*>(xp + 4);
            v0.x += outacc[m][0]; v0.y += outacc[m][1];
            v0.z += outacc[m][2]; v0.w += outacc[m][3];
            v1.x += outacc[m][4]; v1.y += outacc[m][5];
            v1.z += outacc[m][6]; v1.w += outacc[m][7];
            *reinterpret_cast<float4*>(dst)     = v0;
            *reinterpret_cast<float4*>(dst + 4) = v1;
        }
    }
}

// ---------------------------------------------------------------------------
extern "C" void kernel_launch(void* const* d_in, const int* in_sizes, int n_in,
                              void* d_out, int out_size) {
    const float* x        = (const float*)d_in[0];
    const float* router_w = (const float*)d_in[1];
    const float* router_b = (const float*)d_in[2];
    const float* dw_w     = (const float*)d_in[3];
    // d_in[4] = dw_b: cancels in LayerNorm (constant per-channel shift), unused
    const float* ln_w     = (const float*)d_in[5];
    const float* ln_b     = (const float*)d_in[6];
    const float* pw_in_w  = (const float*)d_in[7];
    const float* pw_in_b  = (const float*)d_in[8];
    const float* pw_out_w = (const float*)d_in[9];
    const float* pw_out_b = (const float*)d_in[10];
    float* out = (float*)d_out;

    const int B = in_sizes[0] / (64 * 8 * 128 * 128);
    const int N = B * 256;           // patches
    const int smem_bytes = (int)sizeof(SmemLayout);

    cudaFuncSetAttribute(moe_main_kernel,
                         cudaFuncAttributeMaxDynamicSharedMemorySize, smem_bytes);

    router_kernel<<<N, 256>>>(x, router_w, router_b);
    moe_main_kernel<<<N * 8, 256, smem_bytes>>>(
        x, dw_w, ln_w, ln_b, pw_in_w, pw_in_b, pw_out_w, pw_out_b, out);
}

// round 4
// speedup vs baseline: 1.2236x; 1.2236x over previous
#include <cuda_runtime.h>
#include <math.h>

// Problem constants (fixed shapes per metadata)
//   x: [B=2, C=64, L=8, H=128, W=128] fp32
//   patches P=8 -> nH=nW=16, N = B*256 patches, 8 L-slices each

typedef unsigned long long u64;

__device__ int   g_topi[2048];
__device__ float g_topw[2048];

__device__ __forceinline__ u64 pack2(float a, float b) {
    u64 r; asm("mov.b64 %0, {%1, %2};" : "=l"(r) : "f"(a), "f"(b)); return r;
}
__device__ __forceinline__ float2 unpack2(u64 v) {
    float2 r; asm("mov.b64 {%0, %1}, %2;" : "=f"(r.x), "=f"(r.y) : "l"(v)); return r;
}
__device__ __forceinline__ void fma2(u64 &d, u64 a, u64 b) {
    asm("fma.rn.f32x2 %0, %1, %2, %0;" : "+l"(d) : "l"(a), "l"(b));
}

// Shared memory layout.
// Activation arrays padded to stride 68: for LDS/STS.128 with row index = lane,
// each quad-phase's 8 lanes tile all 32 banks -> conflict-free vector access.
// Weight arrays stride 65 (odd) so per-lane rows map to 32 distinct banks for
// scalar reads.
// gdw is a union: depthwise weights during stage/depthwise phase (3136 floats),
// gated activations (64*68) during pw_in-epilogue -> pw_out phase.
struct SmemLayout {
    float xs  [64 * 68];   // input slice  [c][p]
    float h   [64 * 68];   // LN output [c][p]
    float gdw [64 * 68];   // union {dw[64*49], gated[64*68]}
    float win [128 * 65];  // pw_in weights [o][c]
    float wout[64 * 65];   // pw_out weights [o][c]
    float lnw [64];
    float lnb [64];
    float bin [128];
    float bout[64];
};
// total = (3*4352 + 8320 + 4160 + 320) * 4 = 103,424 bytes -> 2 CTAs/SM

// ---------------------------------------------------------------------------
// Kernel 1: router. One block per patch. 256 threads: 4 threads per channel.
// ---------------------------------------------------------------------------
__global__ __launch_bounds__(256) void router_kernel(
    const float* __restrict__ x,
    const float* __restrict__ rw,
    const float* __restrict__ rb)
{
    __shared__ float rmean[64];
    __shared__ float lg[8];
    const int n  = blockIdx.x;
    const int b  = n >> 8;
    const int ph = (n >> 4) & 15;
    const int pw = n & 15;
    const int t  = threadIdx.x;
    const int c  = t >> 2;
    const int part = t & 3;

    const float* xb = x + ((size_t)(b * 64 + c) * 8) * 16384 + (ph * 8) * 128 + pw * 8;
    float s = 0.f;
    #pragma unroll 4
    for (int k = 0; k < 16; ++k) {
        int rowid = part * 16 + k;          // 0..63 over (l, r)
        int l = rowid >> 3, r = rowid & 7;
        const float* p = xb + (size_t)l * 16384 + r * 128;
        float4 v0 = *reinterpret_cast<const float4*>(p);
        float4 v1 = *reinterpret_cast<const float4*>(p + 4);
        s += v0.x + v0.y + v0.z + v0.w + v1.x + v1.y + v1.z + v1.w;
    }
    s += __shfl_xor_sync(0xffffffffu, s, 1);
    s += __shfl_xor_sync(0xffffffffu, s, 2);
    if (part == 0) rmean[c] = s * (1.0f / 512.0f);
    __syncthreads();

    if (t < 8) {
        float acc = rb[t];
        #pragma unroll 8
        for (int cc = 0; cc < 64; ++cc) acc += rw[t * 64 + cc] * rmean[cc];
        lg[t] = acc;
    }
    __syncthreads();

    if (t == 0) {
        // top-2 with first-index tie-breaking (matches lax.top_k stability)
        int i0 = 0; float v0 = lg[0];
        #pragma unroll
        for (int e = 1; e < 8; ++e) if (lg[e] > v0) { v0 = lg[e]; i0 = e; }
        int i1 = -1; float v1 = -1e30f;
        #pragma unroll
        for (int e = 0; e < 8; ++e) if (e != i0 && lg[e] > v1) { v1 = lg[e]; i1 = e; }
        float w0 = 1.0f / (1.0f + expf(v1 - v0));
        g_topi[n * 2]     = i0;
        g_topi[n * 2 + 1] = i1;
        g_topw[n * 2]     = w0;
        g_topw[n * 2 + 1] = 1.0f - w0;
    }
}

// ---------------------------------------------------------------------------
// Kernel 2: main MoE compute. One CTA per (patch, l) slice. 256 threads.
// out = x + sum_{top2} w_e * f_e(x_slice)
// ---------------------------------------------------------------------------
__global__ __launch_bounds__(256, 2) void moe_main_kernel(
    const float* __restrict__ x,
    const float* __restrict__ dw_w,
    const float* __restrict__ ln_w,
    const float* __restrict__ ln_b,
    const float* __restrict__ pw_in_w,
    const float* __restrict__ pw_in_b,
    const float* __restrict__ pw_out_w,
    const float* __restrict__ pw_out_b,
    float* __restrict__ out)
{
    extern __shared__ char smem_raw[];
    SmemLayout& S = *reinterpret_cast<SmemLayout*>(smem_raw);

    const int t = threadIdx.x;
    const int slice = blockIdx.x;
    const int n  = slice >> 3;
    const int l  = slice & 7;
    const int b  = n >> 8;
    const int ph = (n >> 4) & 15;
    const int pw = n & 15;
    // global base for this (b, l, patch) at channel 0
    const size_t gslice = (size_t)(b * 64) * 8 * 16384 + (size_t)l * 16384
                        + (ph * 8) * 128 + pw * 8;

    // ---- load x slice into smem (padded stride 68) ----
    #pragma unroll
    for (int k = 0; k < 4; ++k) {
        int id = t + k * 256;           // 1024 float4s total
        int c = id >> 4;
        int r = (id >> 1) & 7;
        int half = id & 1;
        const float* src = x + gslice + (size_t)c * (8 * 16384) + r * 128 + half * 4;
        *reinterpret_cast<float4*>(S.xs + c * 68 + r * 8 + half * 4) =
            *reinterpret_cast<const float4*>(src);
    }

    const int   e0i = g_topi[n * 2];
    const int   e1i = g_topi[n * 2 + 1];
    const float w0v = g_topw[n * 2];
    const float w1v = g_topw[n * 2 + 1];

    float outacc[2][8];
    #pragma unroll
    for (int m = 0; m < 2; ++m)
        #pragma unroll
        for (int j = 0; j < 8; ++j) outacc[m][j] = 0.f;

    for (int ei = 0; ei < 2; ++ei) {
        const int   e  = (ei == 0) ? e0i : e1i;
        const float we = (ei == 0) ? w0v : w1v;

        __syncthreads();  // xs ready (iter 0) / prior expert's smem reads done (iter 1)

        // ---- stage expert weights ----
        {
            const float* wsrc = pw_in_w + e * 8192;
            #pragma unroll
            for (int k = 0; k < 8; ++k) {
                int i4 = t + k * 256;     // 2048 float4s
                float4 v = *reinterpret_cast<const float4*>(wsrc + i4 * 4);
                int o = (i4 * 4) >> 6, c = (i4 * 4) & 63;
                float* d = S.win + o * 65 + c;
                d[0] = v.x; d[1] = v.y; d[2] = v.z; d[3] = v.w;
            }
            const float* wsrc2 = pw_out_w + e * 4096;
            #pragma unroll
            for (int k = 0; k < 4; ++k) {
                int i4 = t + k * 256;     // 1024 float4s
                float4 v = *reinterpret_cast<const float4*>(wsrc2 + i4 * 4);
                int o = (i4 * 4) >> 6, c = (i4 * 4) & 63;
                float* d = S.wout + o * 65 + c;
                d[0] = v.x; d[1] = v.y; d[2] = v.z; d[3] = v.w;
            }
            const float* dsrc = dw_w + e * 3136;
            #pragma unroll
            for (int k = 0; k < 4; ++k) {
                int i4 = t + k * 256;
                if (i4 < 784)
                    *reinterpret_cast<float4*>(S.gdw + i4 * 4) =
                        *reinterpret_cast<const float4*>(dsrc + i4 * 4);
            }
            if (t < 64) {
                S.lnw[t]  = ln_w[e * 64 + t];
                S.lnb[t]  = ln_b[e * 64 + t];
                S.bout[t] = pw_out_b[e * 64 + t];
            }
            if (t < 128) S.bin[t] = pw_in_b[e * 128 + t];
        }
        __syncthreads();

        // ---- depthwise 7x7 (SAME on 8x8) + LayerNorm -> S.h ----
        // thread: c = t/4, rows y0 = 2*(t%4), y0+1
        {
            const int c = t >> 2, q = t & 3, y0 = q << 1;
            float a0[8], a1[8];
            #pragma unroll
            for (int i = 0; i < 8; ++i) { a0[i] = 0.f; a1[i] = 0.f; }
            const float* xc = S.xs + c * 68;
            const float* wc = S.gdw + c * 49;
            #pragma unroll
            for (int yy = 0; yy < 8; ++yy) {
                int d0 = yy - y0;            // dy for row y0; row y0+1 has dy = d0-1
                if (d0 < -3 || d0 > 4) continue;
                float inp[14];
                #pragma unroll
                for (int i = 0; i < 3; ++i) { inp[i] = 0.f; inp[11 + i] = 0.f; }
                float4 va = *reinterpret_cast<const float4*>(xc + yy * 8);
                float4 vb = *reinterpret_cast<const float4*>(xc + yy * 8 + 4);
                inp[3] = va.x; inp[4] = va.y; inp[5]  = va.z; inp[6]  = va.w;
                inp[7] = vb.x; inp[8] = vb.y; inp[9]  = vb.z; inp[10] = vb.w;
                if (d0 >= -3 && d0 <= 3) {
                    const float* wr = wc + (d0 + 3) * 7;
                    float wv[7];
                    #pragma unroll
                    for (int j = 0; j < 7; ++j) wv[j] = wr[j];
                    #pragma unroll
                    for (int xx = 0; xx < 8; ++xx)
                        #pragma unroll
                        for (int j = 0; j < 7; ++j)
                            a0[xx] += wv[j] * inp[xx + j];
                }
                int d1 = d0 - 1;
                if (d1 >= -3 && d1 <= 3) {
                    const float* wr = wc + (d1 + 3) * 7;
                    float wv[7];
                    #pragma unroll
                    for (int j = 0; j < 7; ++j) wv[j] = wr[j];
                    #pragma unroll
                    for (int xx = 0; xx < 8; ++xx)
                        #pragma unroll
                        for (int j = 0; j < 7; ++j)
                            a1[xx] += wv[j] * inp[xx + j];
                }
            }
            // LayerNorm over 64 spatial values per channel (4 lanes per channel)
            float s = 0.f, s2 = 0.f;
            #pragma unroll
            for (int i = 0; i < 8; ++i) {
                s  += a0[i] + a1[i];
                s2 += a0[i] * a0[i] + a1[i] * a1[i];
            }
            s  += __shfl_xor_sync(0xffffffffu, s, 1);
            s  += __shfl_xor_sync(0xffffffffu, s, 2);
            s2 += __shfl_xor_sync(0xffffffffu, s2, 1);
            s2 += __shfl_xor_sync(0xffffffffu, s2, 2);
            const float mean = s * 0.015625f;
            const float var  = fmaxf(s2 * 0.015625f - mean * mean, 0.f);
            const float rstd = rsqrtf(var + 1e-5f);
            float* hc = S.h + c * 68;
            #pragma unroll
            for (int xx = 0; xx < 8; ++xx) {
                int p = y0 * 8 + xx;
                hc[p]     = (a0[xx] - mean) * rstd * S.lnw[p]     + S.lnb[p];
                hc[p + 8] = (a1[xx] - mean) * rstd * S.lnw[p + 8] + S.lnb[p + 8];
            }
        }
        __syncthreads();   // h ready; dw (in gdw) dead after this point

        // ---- pw_in GEMM fused with SiLU gating -> S.gdw (gated activations) ----
        // thread tile: o in {og, og+32, og+64, og+96}, p in [p0, p0+8)
        // pairs (og, og+64) and (og+32, og+96) are the (a, g) pairs for gated
        // channels og and og+32.
        {
            const int og = t & 31;
            const int p0 = (t >> 5) << 3;
            u64 acc[4][4];
            #pragma unroll
            for (int m = 0; m < 4; ++m)
                #pragma unroll
                for (int j = 0; j < 4; ++j) acc[m][j] = 0ull;
            #pragma unroll 4
            for (int c = 0; c < 64; ++c) {
                const float* hc = S.h + c * 68 + p0;
                ulonglong2 hA = *reinterpret_cast<const ulonglong2*>(hc);
                ulonglong2 hB = *reinterpret_cast<const ulonglong2*>(hc + 4);
                #pragma unroll
                for (int m = 0; m < 4; ++m) {
                    float w = S.win[(og + 32 * m) * 65 + c];
                    u64 wp = pack2(w, w);
                    fma2(acc[m][0], wp, hA.x);
                    fma2(acc[m][1], wp, hA.y);
                    fma2(acc[m][2], wp, hB.x);
                    fma2(acc[m][3], wp, hB.y);
                }
            }
            // unpack with biases
            float av[4][8];
            #pragma unroll
            for (int m = 0; m < 4; ++m) {
                float bi = S.bin[og + 32 * m];
                #pragma unroll
                for (int k = 0; k < 4; ++k) {
                    float2 u = unpack2(acc[m][k]);
                    av[m][2 * k]     = u.x + bi;
                    av[m][2 * k + 1] = u.y + bi;
                }
            }
            // gated[og]    = silu(av[0]) * av[2]
            // gated[og+32] = silu(av[1]) * av[3]
            #pragma unroll
            for (int pairI = 0; pairI < 2; ++pairI) {
                float* dst = S.gdw + (og + 32 * pairI) * 68 + p0;
                float r[8];
                #pragma unroll
                for (int j = 0; j < 8; ++j) {
                    float a = av[pairI][j];
                    float g = av[pairI + 2][j];
                    r[j] = a / (1.f + __expf(-a)) * g;
                }
                *reinterpret_cast<float4*>(dst)     = make_float4(r[0], r[1], r[2], r[3]);
                *reinterpret_cast<float4*>(dst + 4) = make_float4(r[4], r[5], r[6], r[7]);
            }
        }
        __syncthreads();

        // ---- pw_out GEMM + weighted accumulate into registers ----
        // thread tile: o in {og, og+32}, p in [p0, p0+8)
        {
            const int og = t & 31;
            const int p0 = (t >> 5) << 3;
            u64 acc[2][4];
            #pragma unroll
            for (int m = 0; m < 2; ++m)
                #pragma unroll
                for (int j = 0; j < 4; ++j) acc[m][j] = 0ull;
            #pragma unroll 4
            for (int c = 0; c < 64; ++c) {
                const float* ac = S.gdw + c * 68 + p0;
                ulonglong2 hA = *reinterpret_cast<const ulonglong2*>(ac);
                ulonglong2 hB = *reinterpret_cast<const ulonglong2*>(ac + 4);
                float wa = S.wout[og * 65 + c];
                float wb = S.wout[(og + 32) * 65 + c];
                u64 wpa = pack2(wa, wa);
                u64 wpb = pack2(wb, wb);
                fma2(acc[0][0], wpa, hA.x);
                fma2(acc[0][1], wpa, hA.y);
                fma2(acc[0][2], wpa, hB.x);
                fma2(acc[0][3], wpa, hB.y);
                fma2(acc[1][0], wpb, hA.x);
                fma2(acc[1][1], wpb, hA.y);
                fma2(acc[1][2], wpb, hB.x);
                fma2(acc[1][3], wpb, hB.y);
            }
            #pragma unroll
            for (int m = 0; m < 2; ++m) {
                int o = og + 32 * m;
                float bo = S.bout[o];
                #pragma unroll
                for (int k = 0; k < 4; ++k) {
                    float2 u = unpack2(acc[m][k]);
                    outacc[m][2 * k]     += we * (u.x + bo);
                    outacc[m][2 * k + 1] += we * (u.y + bo);
                }
            }
        }
    }

    // ---- final write: out = x + accumulated expert residuals ----
    // thread (r = t>>5, og = t&31) computed p-range r*8..r*8+7 for channels og, og+32
    {
        const int r  = t >> 5;
        const int og = t & 31;
        #pragma unroll
        for (int m = 0; m < 2; ++m) {
            int c = og + 32 * m;
            const float* xp = S.xs + c * 68 + r * 8;
            float* dst = out + gslice + (size_t)c * (8 * 16384) + r * 128;
            float4 v0 = *reinterpret_cast<const float4*>(xp);
            float4 v1 = *reinterpret_cast<const float4*>(xp + 4);
            v0.x += outacc[m][0]; v0.y += outacc[m][1];
            v0.z += outacc[m][2]; v0.w += outacc[m][3];
            v1.x += outacc[m][4]; v1.y += outacc[m][5];
            v1.z += outacc[m][6]; v1.w += outacc[m][7];
            *reinterpret_cast<float4*>(dst)     = v0;
            *reinterpret_cast<float4*>(dst + 4) = v1;
        }
    }
}

// ---------------------------------------------------------------------------
extern "C" void kernel_launch(void* const* d_in, const int* in_sizes, int n_in,
                              void* d_out, int out_size) {
    const float* x        = (const float*)d_in[0];
    const float* router_w = (const float*)d_in[1];
    const float* router_b = (const float*)d_in[2];
    const float* dw_w     = (const float*)d_in[3];
    // d_in[4] = dw_b: cancels in LayerNorm (constant per-channel shift), unused
    const float* ln_w     = (const float*)d_in[5];
    const float* ln_b     = (const float*)d_in[6];
    const float* pw_in_w  = (const float*)d_in[7];
    const float* pw_in_b  = (const float*)d_in[8];
    const float* pw_out_w = (const float*)d_in[9];
    const float* pw_out_b = (const float*)d_in[10];
    float* out = (float*)d_out;

    const int B = in_sizes[0] / (64 * 8 * 128 * 128);
    const int N = B * 256;           // patches
    const int smem_bytes = (int)sizeof(SmemLayout);

    cudaFuncSetAttribute(moe_main_kernel,
                         cudaFuncAttributeMaxDynamicSharedMemorySize, smem_bytes);

    router_kernel<<<N, 256>>>(x, router_w, router_b);
    moe_main_kernel<<<N * 8, 256, smem_bytes>>>(
        x, dw_w, ln_w, ln_b, pw_in_w, pw_in_b, pw_out_w, pw_out_b, out);
}

// round 5
// speedup vs baseline: 1.9624x; 1.6038x over previous
#include <cuda_runtime.h>
#include <math.h>
#include <stdint.h>

// Problem constants (fixed shapes per metadata)
//   x: [B=2, C=64, L=8, H=128, W=128] fp32
//   patches P=8 -> nH=nW=16, N = B*256 patches, 8 L-slices each

typedef unsigned long long u64;

__device__ int   g_topi[2048];
__device__ float g_topw[2048];

__device__ __forceinline__ u64 pack2(float a, float b) {
    u64 r; asm("mov.b64 %0, {%1, %2};" : "=l"(r) : "f"(a), "f"(b)); return r;
}
__device__ __forceinline__ float2 unpack2(u64 v) {
    float2 r; asm("mov.b64 {%0, %1}, %2;" : "=f"(r.x), "=f"(r.y) : "l"(v)); return r;
}
__device__ __forceinline__ void fma2(u64 &d, u64 a, u64 b) {
    asm("fma.rn.f32x2 %0, %1, %2, %0;" : "+l"(d) : "l"(a), "l"(b));
}
__device__ __forceinline__ uint32_t f2tf32(float f) {
    uint32_t u; asm("cvt.rna.tf32.f32 %0, %1;" : "=r"(u) : "f"(f)); return u;
}
// D += A(tf32,m16k8,row) * B(tf32,k8n8,col), fp32 accum
__device__ __forceinline__ void mma_tf32(float d[4], const uint32_t a[4],
                                         uint32_t b0, uint32_t b1) {
    asm volatile(
        "mma.sync.aligned.m16n8k8.row.col.f32.tf32.tf32.f32 "
        "{%0,%1,%2,%3}, {%4,%5,%6,%7}, {%8,%9}, {%0,%1,%2,%3};"
        : "+f"(d[0]), "+f"(d[1]), "+f"(d[2]), "+f"(d[3])
        : "r"(a[0]), "r"(a[1]), "r"(a[2]), "r"(a[3]), "r"(b0), "r"(b1));
}

// Shared memory layout. All 2-D arrays stride 68 floats:
//  - xs  [c][p]  input (fp32)
//  - ht  [p][c]  LN output, TRANSPOSED, tf32-rounded (GEMM1 B operand)
//  - gdwt        union { dw weights fp32 (64*49) | gated_t[p][c] tf32 (GEMM2 B) }
//  - win [o][c]  pw_in weights, tf32-rounded (A operand): bank (4o+c)%32 conflict-free
//  - wout[o][c]  pw_out weights, tf32-rounded
struct SmemLayout {
    float xs  [64 * 68];
    float ht  [64 * 68];
    float gdwt[64 * 68];
    float win [128 * 68];
    float wout[64 * 68];
    float lnw [64];
    float lnb [64];
    float bin [128];
    float bout[64];
};
// floats = 3*4352 + 8704 + 4352 + 320 = 26432 -> 105,728 B -> 2 CTAs/SM (211.5 KB < 228 KB)

// ---------------------------------------------------------------------------
// Kernel 1: router. One block per patch. 256 threads: 4 threads per channel.
// ---------------------------------------------------------------------------
__global__ __launch_bounds__(256) void router_kernel(
    const float* __restrict__ x,
    const float* __restrict__ rw,
    const float* __restrict__ rb)
{
    __shared__ float rmean[64];
    __shared__ float lg[8];
    const int n  = blockIdx.x;
    const int b  = n >> 8;
    const int ph = (n >> 4) & 15;
    const int pw = n & 15;
    const int t  = threadIdx.x;
    const int c  = t >> 2;
    const int part = t & 3;

    const float* xb = x + ((size_t)(b * 64 + c) * 8) * 16384 + (ph * 8) * 128 + pw * 8;
    float s = 0.f;
    #pragma unroll 4
    for (int k = 0; k < 16; ++k) {
        int rowid = part * 16 + k;          // 0..63 over (l, r)
        int l = rowid >> 3, r = rowid & 7;
        const float* p = xb + (size_t)l * 16384 + r * 128;
        float4 v0 = *reinterpret_cast<const float4*>(p);
        float4 v1 = *reinterpret_cast<const float4*>(p + 4);
        s += v0.x + v0.y + v0.z + v0.w + v1.x + v1.y + v1.z + v1.w;
    }
    s += __shfl_xor_sync(0xffffffffu, s, 1);
    s += __shfl_xor_sync(0xffffffffu, s, 2);
    if (part == 0) rmean[c] = s * (1.0f / 512.0f);
    __syncthreads();

    if (t < 8) {
        float acc = rb[t];
        #pragma unroll 8
        for (int cc = 0; cc < 64; ++cc) acc += rw[t * 64 + cc] * rmean[cc];
        lg[t] = acc;
    }
    __syncthreads();

    if (t == 0) {
        int i0 = 0; float v0 = lg[0];
        #pragma unroll
        for (int e = 1; e < 8; ++e) if (lg[e] > v0) { v0 = lg[e]; i0 = e; }
        int i1 = -1; float v1 = -1e30f;
        #pragma unroll
        for (int e = 0; e < 8; ++e) if (e != i0 && lg[e] > v1) { v1 = lg[e]; i1 = e; }
        float w0 = 1.0f / (1.0f + expf(v1 - v0));
        g_topi[n * 2]     = i0;
        g_topi[n * 2 + 1] = i1;
        g_topw[n * 2]     = w0;
        g_topw[n * 2 + 1] = 1.0f - w0;
    }
}

// ---------------------------------------------------------------------------
// Kernel 2: main MoE compute. One CTA per (patch, l) slice. 256 threads.
// out = x + sum_{top2} w_e * f_e(x_slice)
// GEMMs via tf32 mma.sync.m16n8k8.
// ---------------------------------------------------------------------------
__global__ __launch_bounds__(256, 2) void moe_main_kernel(
    const float* __restrict__ x,
    const float* __restrict__ dw_w,
    const float* __restrict__ ln_w,
    const float* __restrict__ ln_b,
    const float* __restrict__ pw_in_w,
    const float* __restrict__ pw_in_b,
    const float* __restrict__ pw_out_w,
    const float* __restrict__ pw_out_b,
    float* __restrict__ out)
{
    extern __shared__ char smem_raw[];
    SmemLayout& S = *reinterpret_cast<SmemLayout*>(smem_raw);

    const int t    = threadIdx.x;
    const int warp = t >> 5;
    const int lane = t & 31;
    const int r    = lane >> 2;   // mma groupID
    const int tig  = lane & 3;    // mma threadID-in-group
    const int wo   = warp & 3;    // o-chunk (16 rows) index
    const int ph   = warp >> 2;   // p-half (32 cols) index
    const int pb   = ph * 32;

    const int slice = blockIdx.x;
    const int n  = slice >> 3;
    const int l  = slice & 7;
    const int b  = n >> 8;
    const int phh = (n >> 4) & 15;
    const int pww = n & 15;
    const size_t gslice = (size_t)(b * 64) * 8 * 16384 + (size_t)l * 16384
                        + (phh * 8) * 128 + pww * 8;

    // ---- load x slice into smem xs[c][p] (stride 68) ----
    #pragma unroll
    for (int k = 0; k < 4; ++k) {
        int id = t + k * 256;           // 1024 float4s
        int c = id >> 4;
        int rr = (id >> 1) & 7;
        int half = id & 1;
        const float* src = x + gslice + (size_t)c * (8 * 16384) + rr * 128 + half * 4;
        *reinterpret_cast<float4*>(S.xs + c * 68 + rr * 8 + half * 4) =
            *reinterpret_cast<const float4*>(src);
    }

    const int   e0i = g_topi[n * 2];
    const int   e1i = g_topi[n * 2 + 1];
    const float w0v = g_topw[n * 2];
    const float w1v = g_topw[n * 2 + 1];

    float outacc[4][4];        // pw_out result accum across experts (mma D layout)
    #pragma unroll
    for (int nt = 0; nt < 4; ++nt)
        #pragma unroll
        for (int j = 0; j < 4; ++j) outacc[nt][j] = 0.f;

    for (int ei = 0; ei < 2; ++ei) {
        const int   e  = (ei == 0) ? e0i : e1i;
        const float we = (ei == 0) ? w0v : w1v;

        __syncthreads();  // xs ready (iter 0) / prior expert's reads done (iter 1)

        // ---- stage expert weights (pw weights pre-converted to tf32) ----
        {
            const float* wsrc = pw_in_w + e * 8192;
            #pragma unroll
            for (int k = 0; k < 8; ++k) {
                int i4 = t + k * 256;     // 2048 float4s [o][c]
                float4 v = *reinterpret_cast<const float4*>(wsrc + i4 * 4);
                int o = i4 >> 4, cb = (i4 & 15) * 4;
                uint4 tv = make_uint4(f2tf32(v.x), f2tf32(v.y), f2tf32(v.z), f2tf32(v.w));
                *reinterpret_cast<uint4*>(S.win + o * 68 + cb) = tv;
            }
            const float* wsrc2 = pw_out_w + e * 4096;
            #pragma unroll
            for (int k = 0; k < 4; ++k) {
                int i4 = t + k * 256;     // 1024 float4s
                float4 v = *reinterpret_cast<const float4*>(wsrc2 + i4 * 4);
                int o = i4 >> 4, cb = (i4 & 15) * 4;
                uint4 tv = make_uint4(f2tf32(v.x), f2tf32(v.y), f2tf32(v.z), f2tf32(v.w));
                *reinterpret_cast<uint4*>(S.wout + o * 68 + cb) = tv;
            }
            const float* dsrc = dw_w + e * 3136;
            #pragma unroll
            for (int k = 0; k < 4; ++k) {
                int i4 = t + k * 256;
                if (i4 < 784)
                    *reinterpret_cast<float4*>(S.gdwt + i4 * 4) =
                        *reinterpret_cast<const float4*>(dsrc + i4 * 4);
            }
            if (t < 64) {
                S.lnw[t]  = ln_w[e * 64 + t];
                S.lnb[t]  = ln_b[e * 64 + t];
                S.bout[t] = pw_out_b[e * 64 + t];
            }
            if (t < 128) S.bin[t] = pw_in_b[e * 128 + t];
        }
        __syncthreads();

        // ---- depthwise 7x7 (SAME on 8x8) + LayerNorm -> ht[p][c] (tf32) ----
        // thread: c = t/4, rows y0 = 2*(t%4), y0+1; f32x2-packed over the row pair
        {
            const int c = t >> 2, q = t & 3, y0 = q << 1;
            u64 acc[8];
            #pragma unroll
            for (int i = 0; i < 8; ++i) acc[i] = 0ull;
            const float* xc = S.xs + c * 68;
            const float* wc = S.gdwt + c * 49;
            #pragma unroll
            for (int yy = 0; yy < 8; ++yy) {
                int d0 = yy - y0;            // dy for row y0; row y0+1 has dy = d0-1
                if (d0 < -3 || d0 > 4) continue;
                float inp[14];
                #pragma unroll
                for (int i = 0; i < 3; ++i) { inp[i] = 0.f; inp[11 + i] = 0.f; }
                float4 va = *reinterpret_cast<const float4*>(xc + yy * 8);
                float4 vb = *reinterpret_cast<const float4*>(xc + yy * 8 + 4);
                inp[3] = va.x; inp[4] = va.y; inp[5]  = va.z; inp[6]  = va.w;
                inp[7] = vb.x; inp[8] = vb.y; inp[9]  = vb.z; inp[10] = vb.w;
                u64 ip[14];
                #pragma unroll
                for (int i = 0; i < 14; ++i) ip[i] = pack2(inp[i], inp[i]);
                const bool v0 = (d0 >= -3) && (d0 <= 3);
                const bool v1 = (d0 >= -2);            // d0 <= 4 implies d0-1 <= 3
                u64 wp[7];
                #pragma unroll
                for (int j = 0; j < 7; ++j) {
                    float a = v0 ? wc[(d0 + 3) * 7 + j] : 0.f;
                    float g = v1 ? wc[(d0 + 2) * 7 + j] : 0.f;
                    wp[j] = pack2(a, g);
                }
                #pragma unroll
                for (int xx = 0; xx < 8; ++xx)
                    #pragma unroll
                    for (int j = 0; j < 7; ++j)
                        fma2(acc[xx], wp[j], ip[xx + j]);
            }
            float a0[8], a1[8];
            float s = 0.f, s2 = 0.f;
            #pragma unroll
            for (int i = 0; i < 8; ++i) {
                float2 u = unpack2(acc[i]);
                a0[i] = u.x; a1[i] = u.y;
                s  += u.x + u.y;
                s2 += u.x * u.x + u.y * u.y;
            }
            s  += __shfl_xor_sync(0xffffffffu, s, 1);
            s  += __shfl_xor_sync(0xffffffffu, s, 2);
            s2 += __shfl_xor_sync(0xffffffffu, s2, 1);
            s2 += __shfl_xor_sync(0xffffffffu, s2, 2);
            const float mean = s * 0.015625f;
            const float var  = fmaxf(s2 * 0.015625f - mean * mean, 0.f);
            const float rstd = rsqrtf(var + 1e-5f);
            #pragma unroll
            for (int xx = 0; xx < 8; ++xx) {
                int p0 = y0 * 8 + xx;
                float h0 = (a0[xx] - mean) * rstd * S.lnw[p0]     + S.lnb[p0];
                float h1 = (a1[xx] - mean) * rstd * S.lnw[p0 + 8] + S.lnb[p0 + 8];
                *reinterpret_cast<uint32_t*>(S.ht + p0 * 68 + c)       = f2tf32(h0);
                *reinterpret_cast<uint32_t*>(S.ht + (p0 + 8) * 68 + c) = f2tf32(h1);
            }
        }
        __syncthreads();   // ht ready; dw (in gdwt) dead after this point

        // ---- GEMM1 (pw_in, tf32 mma) fused with SiLU gating -> gdwt[p][c] ----
        // warp (wo, ph): a-rows [16wo,16wo+16), g-rows [64+16wo, ...), p [pb, pb+32)
        {
            const int oa = 16 * wo;
            float accA[4][4], accG[4][4];
            #pragma unroll
            for (int nt = 0; nt < 4; ++nt)
                #pragma unroll
                for (int j = 0; j < 4; ++j) { accA[nt][j] = 0.f; accG[nt][j] = 0.f; }
            const uint32_t* winU = reinterpret_cast<const uint32_t*>(S.win);
            const uint32_t* htU  = reinterpret_cast<const uint32_t*>(S.ht);
            #pragma unroll
            for (int ks = 0; ks < 8; ++ks) {
                const int c0 = ks * 8 + tig;
                uint32_t aA[4], aG[4];
                aA[0] = winU[(oa + r) * 68 + c0];
                aA[1] = winU[(oa + r + 8) * 68 + c0];
                aA[2] = winU[(oa + r) * 68 + c0 + 4];
                aA[3] = winU[(oa + r + 8) * 68 + c0 + 4];
                aG[0] = winU[(64 + oa + r) * 68 + c0];
                aG[1] = winU[(64 + oa + r + 8) * 68 + c0];
                aG[2] = winU[(64 + oa + r) * 68 + c0 + 4];
                aG[3] = winU[(64 + oa + r + 8) * 68 + c0 + 4];
                #pragma unroll
                for (int nt = 0; nt < 4; ++nt) {
                    const int p0 = pb + nt * 8;
                    uint32_t b0 = htU[(p0 + r) * 68 + c0];
                    uint32_t b1 = htU[(p0 + r) * 68 + c0 + 4];
                    mma_tf32(accA[nt], aA, b0, b1);
                    mma_tf32(accG[nt], aG, b0, b1);
                }
            }
            // epilogue: bias + silu gate, store transposed tf32
            const float biA0 = S.bin[oa + r],       biA1 = S.bin[oa + r + 8];
            const float biG0 = S.bin[64 + oa + r],  biG1 = S.bin[64 + oa + r + 8];
            uint32_t* gU = reinterpret_cast<uint32_t*>(S.gdwt);
            #pragma unroll
            for (int nt = 0; nt < 4; ++nt) {
                const int p0 = pb + nt * 8 + 2 * tig;
                #pragma unroll
                for (int j = 0; j < 4; ++j) {
                    const float a = accA[nt][j] + ((j < 2) ? biA0 : biA1);
                    const float g = accG[nt][j] + ((j < 2) ? biG0 : biG1);
                    const float ga = a / (1.f + __expf(-a)) * g;
                    const int p  = p0 + (j & 1);
                    const int co = oa + r + ((j < 2) ? 0 : 8);
                    gU[p * 68 + co] = f2tf32(ga);
                }
            }
        }
        __syncthreads();

        // ---- GEMM2 (pw_out, tf32 mma): accumulate we*(D + bias) in registers ----
        // warp (wo, ph): o2-rows [16wo, 16wo+16), p [pb, pb+32)
        {
            const int o2 = 16 * wo;
            float accO[4][4];
            #pragma unroll
            for (int nt = 0; nt < 4; ++nt)
                #pragma unroll
                for (int j = 0; j < 4; ++j) accO[nt][j] = 0.f;
            const uint32_t* woU = reinterpret_cast<const uint32_t*>(S.wout);
            const uint32_t* gU  = reinterpret_cast<const uint32_t*>(S.gdwt);
            #pragma unroll
            for (int ks = 0; ks < 8; ++ks) {
                const int c0 = ks * 8 + tig;
                uint32_t aO[4];
                aO[0] = woU[(o2 + r) * 68 + c0];
                aO[1] = woU[(o2 + r + 8) * 68 + c0];
                aO[2] = woU[(o2 + r) * 68 + c0 + 4];
                aO[3] = woU[(o2 + r + 8) * 68 + c0 + 4];
                #pragma unroll
                for (int nt = 0; nt < 4; ++nt) {
                    const int p0 = pb + nt * 8;
                    uint32_t b0 = gU[(p0 + r) * 68 + c0];
                    uint32_t b1 = gU[(p0 + r) * 68 + c0 + 4];
                    mma_tf32(accO[nt], aO, b0, b1);
                }
            }
            const float bo0 = S.bout[o2 + r], bo1 = S.bout[o2 + r + 8];
            #pragma unroll
            for (int nt = 0; nt < 4; ++nt)
                #pragma unroll
                for (int j = 0; j < 4; ++j)
                    outacc[nt][j] += we * (accO[nt][j] + ((j < 2) ? bo0 : bo1));
        }
    }

    // ---- final write: out = x + accumulated expert residuals ----
    // thread owns channels {16wo+r, 16wo+r+8}, p = pb + 8nt + 2tig (+1)
    {
        const int o2 = 16 * wo;
        #pragma unroll
        for (int nt = 0; nt < 4; ++nt) {
            const int p0 = pb + nt * 8 + 2 * tig;
            const int rr = p0 >> 3, col = p0 & 7;
            #pragma unroll
            for (int half = 0; half < 2; ++half) {
                const int ch = o2 + r + half * 8;
                float2 xv = *reinterpret_cast<const float2*>(S.xs + ch * 68 + p0);
                float2 ov;
                ov.x = xv.x + outacc[nt][half * 2];
                ov.y = xv.y + outacc[nt][half * 2 + 1];
                float* dst = out + gslice + (size_t)ch * (8 * 16384) + rr * 128 + col;
                *reinterpret_cast<float2*>(dst) = ov;
            }
        }
    }
}

// ---------------------------------------------------------------------------
extern "C" void kernel_launch(void* const* d_in, const int* in_sizes, int n_in,
                              void* d_out, int out_size) {
    const float* x        = (const float*)d_in[0];
    const float* router_w = (const float*)d_in[1];
    const float* router_b = (const float*)d_in[2];
    const float* dw_w     = (const float*)d_in[3];
    // d_in[4] = dw_b: cancels in LayerNorm (constant per-channel shift), unused
    const float* ln_w     = (const float*)d_in[5];
    const float* ln_b     = (const float*)d_in[6];
    const float* pw_in_w  = (const float*)d_in[7];
    const float* pw_in_b  = (const float*)d_in[8];
    const float* pw_out_w = (const float*)d_in[9];
    const float* pw_out_b = (const float*)d_in[10];
    float* out = (float*)d_out;

    const int B = in_sizes[0] / (64 * 8 * 128 * 128);
    const int N = B * 256;           // patches
    const int smem_bytes = (int)sizeof(SmemLayout);

    cudaFuncSetAttribute(moe_main_kernel,
                         cudaFuncAttributeMaxDynamicSharedMemorySize, smem_bytes);

    router_kernel<<<N, 256>>>(x, router_w, router_b);
    moe_main_kernel<<<N * 8, 256, smem_bytes>>>(
        x, dw_w, ln_w, ln_b, pw_in_w, pw_in_b, pw_out_w, pw_out_b, out);
}

// round 8
// speedup vs baseline: 2.3777x; 1.2117x over previous
#include <cuda_runtime.h>
#include <cuda_bf16.h>
#include <math.h>
#include <stdint.h>

// x: [B=2, C=64, L=8, H=128, W=128] fp32; P=8 patches; top-2 of 8 experts.
// out = x + sum_top2 w_e * f_e(x_slice); GEMMs via mma.sync.m16n8k16 (bf16).

typedef unsigned long long u64;

__device__ int   g_topi[2048];
__device__ float g_topw[2048];

__device__ __forceinline__ u64 pack2(float a, float b) {
    u64 r; asm("mov.b64 %0, {%1, %2};" : "=l"(r) : "f"(a), "f"(b)); return r;
}
__device__ __forceinline__ float2 unpack2(u64 v) {
    float2 r; asm("mov.b64 {%0, %1}, %2;" : "=f"(r.x), "=f"(r.y) : "l"(v)); return r;
}
__device__ __forceinline__ void fma2(u64 &d, u64 a, u64 b) {
    asm("fma.rn.f32x2 %0, %1, %2, %0;" : "+l"(d) : "l"(a), "l"(b));
}
// D += A(bf16,m16k16,row) * B(bf16,k16n8,col), fp32 accum
__device__ __forceinline__ void mma_bf16(float d[4], const uint32_t a[4],
                                         uint32_t b0, uint32_t b1) {
    asm volatile(
        "mma.sync.aligned.m16n8k16.row.col.f32.bf16.bf16.f32 "
        "{%0,%1,%2,%3}, {%4,%5,%6,%7}, {%8,%9}, {%0,%1,%2,%3};"
        : "+f"(d[0]), "+f"(d[1]), "+f"(d[2]), "+f"(d[3])
        : "r"(a[0]), "r"(a[1]), "r"(a[2]), "r"(a[3]), "r"(b0), "r"(b1));
}
__device__ __forceinline__ uint32_t bf2pack(float a, float b) {
    __nv_bfloat162 v = __floats2bfloat162_rn(a, b);
    return *reinterpret_cast<uint32_t*>(&v);
}
// Activation-tile swizzle: element index for [p][c], stride 72, with the c-group
// XORed by (p>>3) so depthwise stores (p varying by 8) spread banks, while
// fragment loads (p>>3 constant within a warp's n-tile) remain conflict-free.
__device__ __forceinline__ int HSW(int p, int c) {
    return p * 72 + (c ^ (((p >> 3) << 3) & 56));
}

// Shared memory layout.
//  win [o][c] bf16 stride 72 (straight; A-fragment bank = 4o+tig, conflict-free)
//  wout[o][c] bf16 stride 72
//  ht  [p][c] bf16 stride 72, HSW swizzle (GEMM1 B operand)
//  xs  [c][p] fp32 stride 68
//  dwg: union { dw fp32 3136 | gated bf16 [64][72] HSW (GEMM2 B operand) }
struct SmemLayout {
    __nv_bfloat16 win [128 * 72];   // 18432 B
    __nv_bfloat16 wout[64 * 72];    //  9216 B
    __nv_bfloat16 ht  [64 * 72];    //  9216 B
    float xs [64 * 68];             // 17408 B
    float dwg[3136];                // 12544 B (gated bf16 needs 9216)
    float lnw[64];
    float lnb[64];
    float bin[128];
    float bout[64];
};
// total ~= 68,096 B -> 2 CTAs/SM at 128 regs

// ---------------------------------------------------------------------------
// Kernel 1: router. One block per patch.
// ---------------------------------------------------------------------------
__global__ __launch_bounds__(256) void router_kernel(
    const float* __restrict__ x,
    const float* __restrict__ rw,
    const float* __restrict__ rb)
{
    __shared__ float rmean[64];
    __shared__ float lg[8];
    const int n  = blockIdx.x;
    const int b  = n >> 8;
    const int ph = (n >> 4) & 15;
    const int pw = n & 15;
    const int t  = threadIdx.x;
    const int c  = t >> 2;
    const int part = t & 3;

    const float* xb = x + ((size_t)(b * 64 + c) * 8) * 16384 + (ph * 8) * 128 + pw * 8;
    float s = 0.f;
    #pragma unroll 4
    for (int k = 0; k < 16; ++k) {
        int rowid = part * 16 + k;
        int l = rowid >> 3, r = rowid & 7;
        const float* p = xb + (size_t)l * 16384 + r * 128;
        float4 v0 = *reinterpret_cast<const float4*>(p);
        float4 v1 = *reinterpret_cast<const float4*>(p + 4);
        s += v0.x + v0.y + v0.z + v0.w + v1.x + v1.y + v1.z + v1.w;
    }
    s += __shfl_xor_sync(0xffffffffu, s, 1);
    s += __shfl_xor_sync(0xffffffffu, s, 2);
    if (part == 0) rmean[c] = s * (1.0f / 512.0f);
    __syncthreads();

    if (t < 8) {
        float acc = rb[t];
        #pragma unroll 8
        for (int cc = 0; cc < 64; ++cc) acc += rw[t * 64 + cc] * rmean[cc];
        lg[t] = acc;
    }
    __syncthreads();

    if (t == 0) {
        int i0 = 0; float v0 = lg[0];
        #pragma unroll
        for (int e = 1; e < 8; ++e) if (lg[e] > v0) { v0 = lg[e]; i0 = e; }
        int i1 = -1; float v1 = -1e30f;
        #pragma unroll
        for (int e = 0; e < 8; ++e) if (e != i0 && lg[e] > v1) { v1 = lg[e]; i1 = e; }
        float w0 = 1.0f / (1.0f + expf(v1 - v0));
        g_topi[n * 2]     = i0;
        g_topi[n * 2 + 1] = i1;
        g_topw[n * 2]     = w0;
        g_topw[n * 2 + 1] = 1.0f - w0;
    }
}

// ---------------------------------------------------------------------------
// Kernel 2: main MoE compute. One CTA per (patch, l) slice. 256 threads.
// ---------------------------------------------------------------------------
__global__ __launch_bounds__(256, 2) void moe_main_kernel(
    const float* __restrict__ x,
    const float* __restrict__ dw_w,
    const float* __restrict__ ln_w,
    const float* __restrict__ ln_b,
    const float* __restrict__ pw_in_w,
    const float* __restrict__ pw_in_b,
    const float* __restrict__ pw_out_w,
    const float* __restrict__ pw_out_b,
    float* __restrict__ out)
{
    extern __shared__ char smem_raw[];
    SmemLayout& S = *reinterpret_cast<SmemLayout*>(smem_raw);

    const int t    = threadIdx.x;
    const int warp = t >> 5;
    const int lane = t & 31;
    const int r    = lane >> 2;   // mma groupID
    const int tig  = lane & 3;    // mma threadID-in-group
    const int wo   = warp & 3;    // o-chunk (16 rows)
    const int wh   = warp >> 2;   // p-half (32 cols)
    const int pb   = wh * 32;

    const int slice = blockIdx.x;
    const int n  = slice >> 3;
    const int l  = slice & 7;
    const int b  = n >> 8;
    const int phh = (n >> 4) & 15;
    const int pww = n & 15;
    const size_t gslice = (size_t)(b * 64) * 8 * 16384 + (size_t)l * 16384
                        + (phh * 8) * 128 + pww * 8;

    // ---- load x slice into xs[c][p] (stride 68) ----
    #pragma unroll
    for (int k = 0; k < 4; ++k) {
        int id = t + k * 256;
        int c = id >> 4, rr = (id >> 1) & 7, hf = id & 1;
        const float* src = x + gslice + (size_t)c * (8 * 16384) + rr * 128 + hf * 4;
        *reinterpret_cast<float4*>(S.xs + c * 68 + rr * 8 + hf * 4) =
            *reinterpret_cast<const float4*>(src);
    }

    const int   e0i = g_topi[n * 2];
    const int   e1i = g_topi[n * 2 + 1];
    const float w0v = g_topw[n * 2];
    const float w1v = g_topw[n * 2 + 1];

    float outacc[4][4];
    #pragma unroll
    for (int nt = 0; nt < 4; ++nt)
        #pragma unroll
        for (int j = 0; j < 4; ++j) outacc[nt][j] = 0.f;

    for (int ei = 0; ei < 2; ++ei) {
        const int   e  = (ei == 0) ? e0i : e1i;
        const float we = (ei == 0) ? w0v : w1v;

        __syncthreads();  // xs ready (iter 0) / prior expert's tile reads done

        // ---- stage expert weights (bf16) ----
        {
            const float* wsrc = pw_in_w + e * 8192;   // [o][c] 128x64
            #pragma unroll
            for (int k = 0; k < 8; ++k) {
                int i4 = t + k * 256;                 // 2048 float4s
                float4 v = *reinterpret_cast<const float4*>(wsrc + i4 * 4);
                int o = i4 >> 4, cb = (i4 & 15) * 4;
                uint2 pv = make_uint2(bf2pack(v.x, v.y), bf2pack(v.z, v.w));
                *reinterpret_cast<uint2*>(S.win + o * 72 + cb) = pv;
            }
            const float* wsrc2 = pw_out_w + e * 4096; // 64x64
            #pragma unroll
            for (int k = 0; k < 4; ++k) {
                int i4 = t + k * 256;
                float4 v = *reinterpret_cast<const float4*>(wsrc2 + i4 * 4);
                int o = i4 >> 4, cb = (i4 & 15) * 4;
                uint2 pv = make_uint2(bf2pack(v.x, v.y), bf2pack(v.z, v.w));
                *reinterpret_cast<uint2*>(S.wout + o * 72 + cb) = pv;
            }
            const float* dsrc = dw_w + e * 3136;
            #pragma unroll
            for (int k = 0; k < 4; ++k) {
                int i4 = t + k * 256;
                if (i4 < 784)
                    *reinterpret_cast<float4*>(S.dwg + i4 * 4) =
                        *reinterpret_cast<const float4*>(dsrc + i4 * 4);
            }
            if (t < 64) {
                S.lnw[t]  = ln_w[e * 64 + t];
                S.lnb[t]  = ln_b[e * 64 + t];
                S.bout[t] = pw_out_b[e * 64 + t];
            }
            if (t < 128) S.bin[t] = pw_in_b[e * 128 + t];
        }
        __syncthreads();

        // ---- depthwise 7x7 + LayerNorm -> ht[p][c] bf16 (HSW swizzle) ----
        // thread: c = t/4, rows y0 = 2*(t%4), y0+1; f32x2-packed row pair
        {
            const int c = t >> 2, q = t & 3, y0 = q << 1;
            u64 acc[8];
            #pragma unroll
            for (int i = 0; i < 8; ++i) acc[i] = 0ull;
            const float* xc = S.xs + c * 68;
            const float* wc = S.dwg + c * 49;
            #pragma unroll
            for (int yy = 0; yy < 8; ++yy) {
                int d0 = yy - y0;
                if (d0 < -3 || d0 > 4) continue;
                float inp[14];
                #pragma unroll
                for (int i = 0; i < 3; ++i) { inp[i] = 0.f; inp[11 + i] = 0.f; }
                float4 va = *reinterpret_cast<const float4*>(xc + yy * 8);
                float4 vb = *reinterpret_cast<const float4*>(xc + yy * 8 + 4);
                inp[3] = va.x; inp[4] = va.y; inp[5]  = va.z; inp[6]  = va.w;
                inp[7] = vb.x; inp[8] = vb.y; inp[9]  = vb.z; inp[10] = vb.w;
                u64 ip[14];
                #pragma unroll
                for (int i = 0; i < 14; ++i) ip[i] = pack2(inp[i], inp[i]);
                const bool v0 = (d0 >= -3) && (d0 <= 3);
                const bool v1 = (d0 >= -2);
                u64 wp[7];
                #pragma unroll
                for (int j = 0; j < 7; ++j) {
                    float a = v0 ? wc[(d0 + 3) * 7 + j] : 0.f;
                    float g = v1 ? wc[(d0 + 2) * 7 + j] : 0.f;
                    wp[j] = pack2(a, g);
                }
                #pragma unroll
                for (int xx = 0; xx < 8; ++xx)
                    #pragma unroll
                    for (int j = 0; j < 7; ++j)
                        fma2(acc[xx], wp[j], ip[xx + j]);
            }
            float a0[8], a1[8], s = 0.f, s2 = 0.f;
            #pragma unroll
            for (int i = 0; i < 8; ++i) {
                float2 u = unpack2(acc[i]);
                a0[i] = u.x; a1[i] = u.y;
                s  += u.x + u.y;
                s2 += u.x * u.x + u.y * u.y;
            }
            s  += __shfl_xor_sync(0xffffffffu, s, 1);
            s  += __shfl_xor_sync(0xffffffffu, s, 2);
            s2 += __shfl_xor_sync(0xffffffffu, s2, 1);
            s2 += __shfl_xor_sync(0xffffffffu, s2, 2);
            const float mean = s * 0.015625f;
            const float var  = fmaxf(s2 * 0.015625f - mean * mean, 0.f);
            const float rstd = rsqrtf(var + 1e-5f);
            #pragma unroll
            for (int xx = 0; xx < 8; ++xx) {
                int p0 = y0 * 8 + xx;
                float h0 = (a0[xx] - mean) * rstd * S.lnw[p0]     + S.lnb[p0];
                float h1 = (a1[xx] - mean) * rstd * S.lnw[p0 + 8] + S.lnb[p0 + 8];
                S.ht[HSW(p0, c)]     = __float2bfloat16(h0);
                S.ht[HSW(p0 + 8, c)] = __float2bfloat16(h1);
            }
        }
        __syncthreads();   // ht ready; dw (in dwg) dead after this point

        // ---- GEMM1 (bf16 mma) fused with SiLU gating -> gated[p][c] (dwg) ----
        // warp (wo, wh): a-rows [16wo,16wo+16), g-rows [64+16wo,...), p [pb,pb+32)
        {
            const int oa = 16 * wo;
            float accA[4][4], accG[4][4];
            #pragma unroll
            for (int nt = 0; nt < 4; ++nt)
                #pragma unroll
                for (int j = 0; j < 4; ++j) { accA[nt][j] = 0.f; accG[nt][j] = 0.f; }
            #pragma unroll
            for (int ks = 0; ks < 4; ++ks) {
                const int c0 = ks * 16 + 2 * tig;
                uint32_t aA[4], aG[4];
                aA[0] = *reinterpret_cast<const uint32_t*>(S.win + (oa + r) * 72 + c0);
                aA[1] = *reinterpret_cast<const uint32_t*>(S.win + (oa + r + 8) * 72 + c0);
                aA[2] = *reinterpret_cast<const uint32_t*>(S.win + (oa + r) * 72 + c0 + 8);
                aA[3] = *reinterpret_cast<const uint32_t*>(S.win + (oa + r + 8) * 72 + c0 + 8);
                aG[0] = *reinterpret_cast<const uint32_t*>(S.win + (64 + oa + r) * 72 + c0);
                aG[1] = *reinterpret_cast<const uint32_t*>(S.win + (64 + oa + r + 8) * 72 + c0);
                aG[2] = *reinterpret_cast<const uint32_t*>(S.win + (64 + oa + r) * 72 + c0 + 8);
                aG[3] = *reinterpret_cast<const uint32_t*>(S.win + (64 + oa + r + 8) * 72 + c0 + 8);
                #pragma unroll
                for (int nt = 0; nt < 4; ++nt) {
                    const int p0 = pb + nt * 8;
                    uint32_t b0 = *reinterpret_cast<const uint32_t*>(S.ht + HSW(p0 + r, c0));
                    uint32_t b1 = *reinterpret_cast<const uint32_t*>(S.ht + HSW(p0 + r, c0 + 8));
                    mma_bf16(accA[nt], aA, b0, b1);
                    mma_bf16(accG[nt], aG, b0, b1);
                }
            }
            // epilogue: bias + silu gate, store bf16 gated tile (HSW)
            const float biA0 = S.bin[oa + r],       biA1 = S.bin[oa + r + 8];
            const float biG0 = S.bin[64 + oa + r],  biG1 = S.bin[64 + oa + r + 8];
            __nv_bfloat16* GT = reinterpret_cast<__nv_bfloat16*>(S.dwg);
            #pragma unroll
            for (int nt = 0; nt < 4; ++nt) {
                const int p0 = pb + nt * 8 + 2 * tig;
                #pragma unroll
                for (int j = 0; j < 4; ++j) {
                    const float a = accA[nt][j] + ((j < 2) ? biA0 : biA1);
                    const float g = accG[nt][j] + ((j < 2) ? biG0 : biG1);
                    const float ga = a / (1.f + __expf(-a)) * g;
                    const int p  = p0 + (j & 1);
                    const int co = oa + r + ((j < 2) ? 0 : 8);
                    GT[HSW(p, co)] = __float2bfloat16(ga);
                }
            }
        }
        __syncthreads();

        // ---- GEMM2 (bf16 mma): accumulate we*(D + bias) in registers ----
        {
            const int o2 = 16 * wo;
            float accO[4][4];
            #pragma unroll
            for (int nt = 0; nt < 4; ++nt)
                #pragma unroll
                for (int j = 0; j < 4; ++j) accO[nt][j] = 0.f;
            const __nv_bfloat16* GT = reinterpret_cast<const __nv_bfloat16*>(S.dwg);
            #pragma unroll
            for (int ks = 0; ks < 4; ++ks) {
                const int c0 = ks * 16 + 2 * tig;
                uint32_t aO[4];
                aO[0] = *reinterpret_cast<const uint32_t*>(S.wout + (o2 + r) * 72 + c0);
                aO[1] = *reinterpret_cast<const uint32_t*>(S.wout + (o2 + r + 8) * 72 + c0);
                aO[2] = *reinterpret_cast<const uint32_t*>(S.wout + (o2 + r) * 72 + c0 + 8);
                aO[3] = *reinterpret_cast<const uint32_t*>(S.wout + (o2 + r + 8) * 72 + c0 + 8);
                #pragma unroll
                for (int nt = 0; nt < 4; ++nt) {
                    const int p0 = pb + nt * 8;
                    uint32_t b0 = *reinterpret_cast<const uint32_t*>(GT + HSW(p0 + r, c0));
                    uint32_t b1 = *reinterpret_cast<const uint32_t*>(GT + HSW(p0 + r, c0 + 8));
                    mma_bf16(accO[nt], aO, b0, b1);
                }
            }
            const float bo0 = S.bout[o2 + r], bo1 = S.bout[o2 + r + 8];
            #pragma unroll
            for (int nt = 0; nt < 4; ++nt)
                #pragma unroll
                for (int j = 0; j < 4; ++j)
                    outacc[nt][j] += we * (accO[nt][j] + ((j < 2) ? bo0 : bo1));
        }
    }

    // ---- final write: out = x + accumulated expert residuals ----
    // thread owns channels {16wo+r, 16wo+r+8}, p = pb + 8nt + 2tig (+1)
    {
        const int o2 = 16 * wo;
        #pragma unroll
        for (int nt = 0; nt < 4; ++nt) {
            const int p0 = pb + nt * 8 + 2 * tig;
            const int rr = p0 >> 3, col = p0 & 7;
            #pragma unroll
            for (int hf = 0; hf < 2; ++hf) {
                const int ch = o2 + r + hf * 8;
                float2 xv = *reinterpret_cast<const float2*>(S.xs + ch * 68 + p0);
                float2 ov;
                ov.x = xv.x + outacc[nt][hf * 2];
                ov.y = xv.y + outacc[nt][hf * 2 + 1];
                float* dst = out + gslice + (size_t)ch * (8 * 16384) + rr * 128 + col;
                *reinterpret_cast<float2*>(dst) = ov;
            }
        }
    }
}

// ---------------------------------------------------------------------------
extern "C" void kernel_launch(void* const* d_in, const int* in_sizes, int n_in,
                              void* d_out, int out_size) {
    const float* x        = (const float*)d_in[0];
    const float* router_w = (const float*)d_in[1];
    const float* router_b = (const float*)d_in[2];
    const float* dw_w     = (const float*)d_in[3];
    // d_in[4] = dw_b: cancels in LayerNorm, unused
    const float* ln_w     = (const float*)d_in[5];
    const float* ln_b     = (const float*)d_in[6];
    const float* pw_in_w  = (const float*)d_in[7];
    const float* pw_in_b  = (const float*)d_in[8];
    const float* pw_out_w = (const float*)d_in[9];
    const float* pw_out_b = (const float*)d_in[10];
    float* out = (float*)d_out;

    const int B = in_sizes[0] / (64 * 8 * 128 * 128);
    const int N = B * 256;
    const int smem_bytes = (int)sizeof(SmemLayout);

    cudaFuncSetAttribute(moe_main_kernel,
                         cudaFuncAttributeMaxDynamicSharedMemorySize, smem_bytes);

    router_kernel<<<N, 256>>>(x, router_w, router_b);
    moe_main_kernel<<<N * 8, 256, smem_bytes>>>(
        x, dw_w, ln_w, ln_b, pw_in_w, pw_in_b, pw_out_w, pw_out_b, out);
}